// round 2
// baseline (speedup 1.0000x reference)
#include <cuda_runtime.h>

#define NP 8192
#define NQ (2*NP)

__device__ __align__(16) float g_U[NQ*128];
__device__ float g_cd[NQ*32];
__device__ int   g_ci[NQ*32];
__device__ int   g_knn[NQ*16];

__device__ __forceinline__ float leaky(float v){ return fmaxf(v, 0.2f*v); }

// ---------------- KNN: per-thread top-16 over half the candidates ----------------
__global__ void knn_kernel(const float* __restrict__ pos){
    __shared__ float4 tile[128];
    int blk  = blockIdx.x;
    int b    = blk >> 7;
    int rem  = blk & 127;
    int half = rem >> 6;
    int n    = ((rem & 63) << 7) + threadIdx.x;
    const float* pb = pos + b*NP*3;
    float xi = pb[n*3+0], yi = pb[n*3+1], zi = pb[n*3+2];

    float bd[16]; int bi[16];
#pragma unroll
    for (int s=0;s<16;s++){ bd[s]=3.4e38f; bi[s]=0; }
    float worst = 3.4e38f; int wslot = 0;

    const int base0 = half*4096;
    for (int t=0;t<32;t++){
        int j = base0 + (t<<7) + threadIdx.x;
        float x = pb[j*3+0], y = pb[j*3+1], z = pb[j*3+2];
        float sq = x*x; sq = fmaf(y,y,sq); sq = fmaf(z,z,sq);
        __syncthreads();
        tile[threadIdx.x] = make_float4(-2.0f*x, -2.0f*y, -2.0f*z, sq);
        __syncthreads();
        int jb = base0 + (t<<7);
        for (int jj=0;jj<128;jj+=4){
            float4 c0=tile[jj+0], c1=tile[jj+1], c2=tile[jj+2], c3=tile[jj+3];
            float d0 = fmaf(zi,c0.z,fmaf(yi,c0.y,fmaf(xi,c0.x,c0.w)));
            float d1 = fmaf(zi,c1.z,fmaf(yi,c1.y,fmaf(xi,c1.x,c1.w)));
            float d2 = fmaf(zi,c2.z,fmaf(yi,c2.y,fmaf(xi,c2.x,c2.w)));
            float d3 = fmaf(zi,c3.z,fmaf(yi,c3.y,fmaf(xi,c3.x,c3.w)));
            float mn = fminf(fminf(d0,d1),fminf(d2,d3));
            if (mn < worst){
                float dd[4] = {d0,d1,d2,d3};
#pragma unroll
                for (int u=0;u<4;u++){
                    if (dd[u] < worst){
                        int id = jb + jj + u;
#pragma unroll
                        for (int s=0;s<16;s++) if (s==wslot){ bd[s]=dd[u]; bi[s]=id; }
                        worst = bd[0]; wslot = 0;
#pragma unroll
                        for (int s=1;s<16;s++) if (bd[s]>worst){ worst=bd[s]; wslot=s; }
                    }
                }
            }
        }
    }
    long base = ((long)(b*NP + n))*32 + (long)half*16;
#pragma unroll
    for (int s=0;s<16;s++){ g_cd[base+s]=bd[s]; g_ci[base+s]=bi[s]; }
}

// rank-merge 2x16 -> 16, tie-break by neighbor index (matches top_k)
__global__ void knn_merge(){
    int q = blockIdx.x*blockDim.x + threadIdx.x;
    float d[32]; int ix[32];
#pragma unroll
    for (int s=0;s<32;s++){ d[s]=g_cd[(long)q*32+s]; ix[s]=g_ci[(long)q*32+s]; }
#pragma unroll
    for (int a=0;a<32;a++){
        int rank=0;
#pragma unroll
        for (int c=0;c<32;c++)
            rank += (d[c] < d[a]) || (d[c]==d[a] && ix[c] < ix[a]);
        if (rank < 16) g_knn[(long)q*16 + rank] = ix[a];
    }
}

// ---------------- U = [W_node; W_edge] * feat, per point ----------------
__global__ void u_kernel(const float* __restrict__ feat,
                         const float* __restrict__ Wn,
                         const float* __restrict__ We){
    extern __shared__ float smC[];
    float* fs = smC;            // [64][128]
    float* ws = smC + 64*128;   // [64][128]  ws[c*128+o] = W[o][c]
    int q0 = blockIdx.x*128;
    int b  = q0 >> 13;
    int n0 = q0 & 8191;
    for (int i=threadIdx.x; i<64*128; i+=256){
        int c = i>>7, nn = i&127;
        fs[i] = feat[((long)(b*64 + c))*NP + n0 + nn];
        int o = nn;
        ws[i] = (o < 64) ? Wn[o*64 + c] : We[(o-64)*64 + c];
    }
    __syncthreads();
    int tx = threadIdx.x & 15, ty = threadIdx.x >> 4;
    float acc[8][8];
#pragma unroll
    for (int i=0;i<8;i++)
#pragma unroll
        for (int j=0;j<8;j++) acc[i][j]=0.f;
#pragma unroll 4
    for (int c=0;c<64;c++){
        float4 a0 = *(const float4*)&fs[c*128 + ty*8];
        float4 a1 = *(const float4*)&fs[c*128 + ty*8 + 4];
        float4 w0 = *(const float4*)&ws[c*128 + tx*8];
        float4 w1 = *(const float4*)&ws[c*128 + tx*8 + 4];
        float av[8] = {a0.x,a0.y,a0.z,a0.w,a1.x,a1.y,a1.z,a1.w};
        float bv[8] = {w0.x,w0.y,w0.z,w0.w,w1.x,w1.y,w1.z,w1.w};
#pragma unroll
        for (int i=0;i<8;i++)
#pragma unroll
            for (int j=0;j<8;j++) acc[i][j] = fmaf(av[i], bv[j], acc[i][j]);
    }
#pragma unroll
    for (int i=0;i<8;i++){
        long q = q0 + ty*8 + i;
        float* r = &g_U[q*128 + tx*8];
        *(float4*)r     = make_float4(acc[i][0],acc[i][1],acc[i][2],acc[i][3]);
        *(float4*)(r+4) = make_float4(acc[i][4],acc[i][5],acc[i][6],acc[i][7]);
    }
}

// ---------------- fused gather + h1 + m1 + m2 + maxpool ----------------
__global__ void edge_main(const float* __restrict__ bn,  const float* __restrict__ be,
                          const float* __restrict__ wm1, const float* __restrict__ vb1,
                          const float* __restrict__ wm2, const float* __restrict__ vb2,
                          float* __restrict__ out){
    extern __shared__ float sm[];
    float* h1T = sm;                  // [64][136]
    float* h2T = h1T + 64*136;        // [64][136]
    float* w1s = h2T + 64*136;        // [c][o] 64x64
    float* w2s = w1s + 64*64;         // [c][o] 64x128
    float* uec = w2s + 64*128;        // [8][64]
    float* red = uec + 512;           // [16][128]
    float* bns = red + 2048;
    float* bes = bns + 64;
    float* b1s = bes + 64;
    float* b2s = b1s + 64;            // 128
    int*   idxs = (int*)(b2s + 128);  // 128

    int q0 = blockIdx.x*8;
    int b  = q0 >> 13;
    int n0 = q0 & 8191;
    int tid = threadIdx.x;

    for (int i=tid;i<4096;i+=256){ int o=i>>6, c=i&63; w1s[c*64 + o]  = wm1[i]; }
    for (int i=tid;i<8192;i+=256){ int o=i>>6, c=i&63; w2s[c*128 + o] = wm2[i]; }
    if (tid<64){ bns[tid]=bn[tid]; bes[tid]=be[tid]; b1s[tid]=vb1[tid]; }
    if (tid<128) b2s[tid]=vb2[tid];
    if (tid<128) idxs[tid] = g_knn[(long)q0*16 + tid];
    for (int i=tid;i<512;i+=256){ int p=i>>6, j=i&63; uec[i] = g_U[(long)(q0+p)*128 + 64 + j]; }
    __syncthreads();

    { // stage A: gather + layer1, store h1T[j][m]
        int m  = tid >> 1;
        int jb = (tid & 1) * 32;
        int p  = m >> 4;
        int nb = idxs[m];
        const float* Ur = &g_U[(long)((b<<13) + nb)*128];
#pragma unroll
        for (int v=0; v<8; v++){
            float4 un = *(const float4*)&Ur[jb + v*4];
            float4 ue = *(const float4*)&Ur[64 + jb + v*4];
            float unv[4] = {un.x,un.y,un.z,un.w};
            float uev[4] = {ue.x,ue.y,ue.z,ue.w};
#pragma unroll
            for (int e=0;e<4;e++){
                int j = jb + v*4 + e;
                float a = leaky(unv[e] + bns[j]);
                float c = leaky(uev[e] - uec[p*64 + j] + bes[j]);
                h1T[j*136 + m] = a + c;
            }
        }
    }
    __syncthreads();

    int tx = tid & 15, ty = tid >> 4;

    { // stage B: M=128 N=64 K=64
        float acc[8][4];
#pragma unroll
        for (int i=0;i<8;i++)
#pragma unroll
            for (int o=0;o<4;o++) acc[i][o]=0.f;
#pragma unroll 4
        for (int c=0;c<64;c++){
            float4 a0 = *(const float4*)&h1T[c*136 + ty*8];
            float4 a1 = *(const float4*)&h1T[c*136 + ty*8 + 4];
            float4 wv = *(const float4*)&w1s[c*64 + tx*4];
            float av[8] = {a0.x,a0.y,a0.z,a0.w,a1.x,a1.y,a1.z,a1.w};
            float bb[4] = {wv.x,wv.y,wv.z,wv.w};
#pragma unroll
            for (int i=0;i<8;i++)
#pragma unroll
                for (int o=0;o<4;o++) acc[i][o] = fmaf(av[i], bb[o], acc[i][o]);
        }
#pragma unroll
        for (int i=0;i<8;i++){
            int m = ty*8 + i;
#pragma unroll
            for (int o=0;o<4;o++)
                h2T[(tx*4+o)*136 + m] = leaky(acc[i][o] + b1s[tx*4+o]);
        }
    }
    __syncthreads();

    { // stage C: M=128 N=128 K=64 + partial max over 8 rows
        float acc[8][8];
#pragma unroll
        for (int i=0;i<8;i++)
#pragma unroll
            for (int o=0;o<8;o++) acc[i][o]=0.f;
#pragma unroll 4
        for (int c=0;c<64;c++){
            float4 a0 = *(const float4*)&h2T[c*136 + ty*8];
            float4 a1 = *(const float4*)&h2T[c*136 + ty*8 + 4];
            float4 w0 = *(const float4*)&w2s[c*128 + tx*8];
            float4 w1 = *(const float4*)&w2s[c*128 + tx*8 + 4];
            float av[8] = {a0.x,a0.y,a0.z,a0.w,a1.x,a1.y,a1.z,a1.w};
            float bb[8] = {w0.x,w0.y,w0.z,w0.w,w1.x,w1.y,w1.z,w1.w};
#pragma unroll
            for (int i=0;i<8;i++)
#pragma unroll
                for (int o=0;o<8;o++) acc[i][o] = fmaf(av[i], bb[o], acc[i][o]);
        }
#pragma unroll
        for (int o=0;o<8;o++){
            float bias = b2s[tx*8+o];
            float pm = -3.4e38f;
#pragma unroll
            for (int i=0;i<8;i++)
                pm = fmaxf(pm, leaky(acc[i][o] + bias));
            red[ty*128 + tx*8 + o] = pm;
        }
    }
    __syncthreads();

    for (int e=tid; e<1024; e+=256){
        int o = e & 127;
        int p = e >> 7;
        float v = fmaxf(red[(2*p)*128 + o], red[(2*p+1)*128 + o]);
        out[((long)(b*128 + o))*NP + n0 + p] = v;
    }
}

extern "C" void kernel_launch(void* const* d_in, const int* in_sizes, int n_in,
                              void* d_out, int out_size){
    const float* feat = (const float*)d_in[0];
    const float* pos  = (const float*)d_in[1];
    const float* Wn   = (const float*)d_in[2];
    const float* bn   = (const float*)d_in[3];
    const float* We   = (const float*)d_in[4];
    const float* be   = (const float*)d_in[5];
    const float* W1   = (const float*)d_in[6];
    const float* b1   = (const float*)d_in[7];
    const float* W2   = (const float*)d_in[8];
    const float* b2   = (const float*)d_in[9];
    float* out = (float*)d_out;

    cudaFuncSetAttribute(u_kernel,  cudaFuncAttributeMaxDynamicSharedMemorySize, 65536);
    cudaFuncSetAttribute(edge_main, cudaFuncAttributeMaxDynamicSharedMemorySize, 131072);

    knn_kernel<<<256,128>>>(pos);
    knn_merge<<<64,256>>>();
    u_kernel<<<128,256,65536>>>(feat, Wn, We);
    edge_main<<<2048,256,130816>>>(bn, be, W1, b1, W2, b2, out);
}